// round 5
// baseline (speedup 1.0000x reference)
#include <cuda_runtime.h>
#include <math.h>

// ---------------- problem constants ----------------
#define BATCH    8192
#define TSTEPS   99
#define DIN      32
#define DH       100
#define GRP      8           // lane-slices per row
#define JT       14          // hidden cols per slice (pad to 16 in xc)
#define RW       16
#define RU       25
#define RP       28          // padded rank (phase-1 accumulator width)
#define SLST     20          // U2 slice stride (words): conflict-free
#define U2ROW    160         // U2 smem row stride = 8*20
#define NCLS     6
#define NTHREADS 128
#define ROWS_CTA 16
#define NGRID    (BATCH / ROWS_CTA)        // 512
#define RT_TOTAL (BATCH * TSTEPS)          // 811008
#define XW_GRID  (RT_TOTAL / 128)          // 6336
#define XW_THREADS 256

// ---------------- device-global prepped weights + scratch ----------------
__device__ float g_Wct[DIN * 128];          // [k][col], col = g*16+jl -> j=g*14+jl
__device__ float g_U1p[112 * RP];           // [slot = jl*8+g][28]
__device__ float g_U2p[RU * U2ROW];         // [r][g*20 + jl]
__device__ float g_bb [112 * 2];            // interleaved (bias_gate, bias_update), j-indexed
__device__ float g_sc [2];                  // sigmoid(zeta), sigmoid(nu)
__device__ float g_xc [(size_t)RT_TOTAL * 128];   // xc[rt][128], col = g*16+jl

// ---------------- packed f32x2 FMA + tanh.approx ----------------
__device__ __forceinline__ void fma2(float2& d, float2 a, float2 b) {
    asm("fma.rn.f32x2 %0, %1, %2, %0;"
        : "+l"(reinterpret_cast<unsigned long long&>(d))
        : "l"(reinterpret_cast<unsigned long long&>(a)),
          "l"(reinterpret_cast<unsigned long long&>(b)));
}
__device__ __forceinline__ float tanha(float x) {
    float r; asm("tanh.approx.f32 %0, %1;" : "=f"(r) : "f"(x)); return r;
}
__device__ __forceinline__ float elem4(float4 v, int e) {
    return (e == 0) ? v.x : (e == 1) ? v.y : (e == 2) ? v.z : v.w;
}

// ---------------- setup: fold / pad / transpose weights ----------------
__global__ void setup_kernel(const float* __restrict__ W1, const float* __restrict__ W2,
                             const float* __restrict__ U1, const float* __restrict__ U2,
                             const float* __restrict__ bg, const float* __restrict__ bu,
                             const float* __restrict__ zeta, const float* __restrict__ nu) {
    int tid = blockIdx.x * blockDim.x + threadIdx.x;
    int nth = gridDim.x * blockDim.x;
    // Wct[k][g*16+jl] = (W1@W2)[k][g*14+jl]  (jl<14, j<100)
    for (int idx = tid; idx < DIN * 128; idx += nth) {
        int k = idx >> 7, c = idx & 127;
        int g = c >> 4, jl = c & 15;
        int j = g * JT + jl;
        float s = 0.f;
        if (jl < JT && j < DH)
            for (int r = 0; r < RW; r++) s = fmaf(W1[k * RW + r], W2[r * DH + j], s);
        g_Wct[idx] = s;
    }
    // U1p[(jl*8+g)*28 + r] = U1[g*14+jl][r]
    for (int idx = tid; idx < 112 * RP; idx += nth) {
        int slot = idx / RP, r = idx % RP;
        int jl = slot >> 3, g = slot & 7;
        int j = g * JT + jl;
        g_U1p[idx] = (j < DH && r < RU) ? U1[j * RU + r] : 0.f;
    }
    // U2p[r*160 + g*20 + c] = U2[r][g*14+c]  (c<14)
    for (int idx = tid; idx < RU * U2ROW; idx += nth) {
        int r = idx / U2ROW, w = idx % U2ROW;
        int g = w / SLST, c = w % SLST;
        int j = g * JT + c;
        g_U2p[idx] = (c < JT && j < DH) ? U2[r * DH + j] : 0.f;
    }
    for (int j = tid; j < 112; j += nth) {
        g_bb[2 * j]     = (j < DH) ? bg[j] : 0.f;
        g_bb[2 * j + 1] = (j < DH) ? bu[j] : 0.f;
    }
    if (tid == 0) {
        g_sc[0] = 1.f / (1.f + expf(-zeta[0]));
        g_sc[1] = 1.f / (1.f + expf(-nu[0]));
    }
}

// ---------------- xw GEMM: g_xc[rt][.] = x_flat[rt][0..31] @ Wct ----------------
__global__ void __launch_bounds__(XW_THREADS)
xw_kernel(const float* __restrict__ x) {
    __shared__ __align__(16) float Wcs[DIN * 128];   // 16 KB
    __shared__ __align__(16) float xts[DIN * 128];   // x transposed: [k][rt_local]

    const int tid = threadIdx.x;
    for (int i = tid; i < DIN * 128; i += XW_THREADS) Wcs[i] = g_Wct[i];

    const float4* xsrc = (const float4*)x + (size_t)blockIdx.x * 1024;
#pragma unroll
    for (int i = 0; i < 4; i++) {
        int fidx = tid * 4 + i;
        int rt_l = fidx >> 3;
        int k4   = (fidx & 7) * 4;
        float4 v = xsrc[fidx];
        xts[(k4 + 0) * 128 + rt_l] = v.x;
        xts[(k4 + 1) * 128 + rt_l] = v.y;
        xts[(k4 + 2) * 128 + rt_l] = v.z;
        xts[(k4 + 3) * 128 + rt_l] = v.w;
    }
    __syncthreads();

    const int rtg = tid >> 3;              // 0..31 (4 rt each)
    const int cg  = tid & 7;               // col chunks at cg*4 + q*32

    float2 acc[4][8];
#pragma unroll
    for (int r = 0; r < 4; r++)
#pragma unroll
        for (int i = 0; i < 8; i++) acc[r][i] = make_float2(0.f, 0.f);

#pragma unroll 4
    for (int k = 0; k < DIN; k++) {
        float4 xv = *(const float4*)(xts + k * 128 + rtg * 4);
#pragma unroll
        for (int q = 0; q < 4; q++) {
            float4 wv = *(const float4*)(Wcs + k * 128 + q * 32 + cg * 4);
            float2 wl = make_float2(wv.x, wv.y);
            float2 wh = make_float2(wv.z, wv.w);
#pragma unroll
            for (int r = 0; r < 4; r++) {
                float xk = elem4(xv, r);
                float2 x2 = make_float2(xk, xk);
                fma2(acc[r][2 * q],     x2, wl);
                fma2(acc[r][2 * q + 1], x2, wh);
            }
        }
    }
#pragma unroll
    for (int r = 0; r < 4; r++) {
        size_t rti = (size_t)blockIdx.x * 128 + rtg * 4 + r;
#pragma unroll
        for (int q = 0; q < 4; q++)
            *(float4*)(g_xc + rti * 128 + q * 32 + cg * 4) =
                make_float4(acc[r][2 * q].x, acc[r][2 * q].y,
                            acc[r][2 * q + 1].x, acc[r][2 * q + 1].y);
    }
}

// ---------------- fused recurrent kernel (no barriers in the t-loop) ----------------
__global__ void __launch_bounds__(NTHREADS, 4)
grnn_kernel(const float* __restrict__ FC, const float* __restrict__ FCb,
            float* __restrict__ out) {
    __shared__ __align__(16) float U1s[112 * RP];    // 12.5 KB
    __shared__ __align__(16) float U2s[RU * U2ROW];  // 16.0 KB
    __shared__ __align__(16) float bbs[112 * 2];     // 0.9 KB

    const int tid = threadIdx.x;
    for (int i = tid; i < 112 * RP; i += NTHREADS) U1s[i] = g_U1p[i];
    for (int i = tid; i < RU * U2ROW; i += NTHREADS) U2s[i] = g_U2p[i];
    for (int i = tid; i < 112 * 2; i += NTHREADS) bbs[i] = g_bb[i];
    __syncthreads();

    const float sz = g_sc[0];
    const float sn = g_sc[1];

    const int lane = tid & 31;
    const int g    = lane & 7;
    const int rw   = lane >> 3;                     // 0..3 row within warp
    const int row  = blockIdx.x * ROWS_CTA + (tid >> 5) * 4 + rw;

    const float* bbp = bbs + (g * JT) * 2;
    const float* px  = g_xc + ((size_t)row * TSTEPS) * 128 + g * 16;

    float2 H[JT / 2];
#pragma unroll
    for (int i = 0; i < JT / 2; i++) H[i] = make_float2(0.f, 0.f);

    // current xc slice (16 floats: 14 real + 2 pad)
    float4 x0 = *(const float4*)(px);
    float4 x1 = *(const float4*)(px + 4);
    float4 x2 = *(const float4*)(px + 8);
    float4 x3 = *(const float4*)(px + 12);

    for (int t = 0; t < TSTEPS; t++) {
        const int off = (t + 1 < TSTEPS) ? (t + 1) * 128 : t * 128;
        float4 n0 = *(const float4*)(px + off);
        float4 n1 = *(const float4*)(px + off + 4);
        float4 n2 = *(const float4*)(px + off + 8);
        float4 n3 = *(const float4*)(px + off + 12);

        // ---- phase 1: partial Hp = H_slice @ U1 ----
        float2 pa[RP / 2];
#pragma unroll
        for (int i = 0; i < RP / 2; i++) pa[i] = make_float2(0.f, 0.f);
#pragma unroll
        for (int jl = 0; jl < JT; jl++) {
            float hv = (jl & 1) ? H[jl >> 1].y : H[jl >> 1].x;
            float2 h2 = make_float2(hv, hv);
            const float4* urow = (const float4*)(U1s + (jl * GRP + g) * RP);
#pragma unroll
            for (int q = 0; q < 7; q++) {
                float4 u = urow[q];
                fma2(pa[2 * q],     h2, make_float2(u.x, u.y));
                fma2(pa[2 * q + 1], h2, make_float2(u.z, u.w));
            }
        }
        // ---- butterfly all-reduce over the 8 slice-lanes ----
#pragma unroll
        for (int i = 0; i < 13; i++) {            // only r<26 matter
            float ax = pa[i].x, ay = pa[i].y;
            ax += __shfl_xor_sync(0xffffffffu, ax, 1);
            ay += __shfl_xor_sync(0xffffffffu, ay, 1);
            ax += __shfl_xor_sync(0xffffffffu, ax, 2);
            ay += __shfl_xor_sync(0xffffffffu, ay, 2);
            ax += __shfl_xor_sync(0xffffffffu, ax, 4);
            ay += __shfl_xor_sync(0xffffffffu, ay, 4);
            pa[i] = make_float2(ax, ay);
        }

        // ---- phase 2: c = xc + Hp @ U2 (slice) ----
        float2 c[8];
        c[0] = make_float2(x0.x, x0.y); c[1] = make_float2(x0.z, x0.w);
        c[2] = make_float2(x1.x, x1.y); c[3] = make_float2(x1.z, x1.w);
        c[4] = make_float2(x2.x, x2.y); c[5] = make_float2(x2.z, x2.w);
        c[6] = make_float2(x3.x, x3.y); c[7] = make_float2(x3.z, x3.w);
#pragma unroll
        for (int r = 0; r < RU; r++) {
            float hp = (r & 1) ? pa[r >> 1].y : pa[r >> 1].x;
            float2 h2 = make_float2(hp, hp);
            const float4* u = (const float4*)(U2s + r * U2ROW + g * SLST);
#pragma unroll
            for (int q = 0; q < 4; q++) {
                float4 uv = u[q];
                fma2(c[2 * q],     h2, make_float2(uv.x, uv.y));
                fma2(c[2 * q + 1], h2, make_float2(uv.z, uv.w));
            }
        }

        // ---- elementwise gate/update (sigmoid = 0.5*tanh(z/2)+0.5) ----
#pragma unroll
        for (int jl = 0; jl < JT; jl++) {
            float2 bb = *(const float2*)(bbp + 2 * jl);
            float cc = (jl & 1) ? c[jl >> 1].y : c[jl >> 1].x;
            float gg = fmaf(0.5f, tanha(0.5f * (cc + bb.x)), 0.5f);
            float hh = tanha(cc + bb.y);
            float ho = (jl & 1) ? H[jl >> 1].y : H[jl >> 1].x;
            float hn = fmaf(gg, ho - sz, fmaf(sn, hh, sz));
            if (jl & 1) H[jl >> 1].y = hn; else H[jl >> 1].x = hn;
        }

        x0 = n0; x1 = n1; x2 = n2; x3 = n3;
    }

    // ---- epilogue: score = H @ FC + FCbias ----
    float s[NCLS];
#pragma unroll
    for (int c = 0; c < NCLS; c++) s[c] = 0.f;
#pragma unroll
    for (int jl = 0; jl < JT; jl++) {
        int jg = g * JT + jl;
        if (jg < DH) {
            float hv = (jl & 1) ? H[jl >> 1].y : H[jl >> 1].x;
#pragma unroll
            for (int c = 0; c < NCLS; c++)
                s[c] = fmaf(hv, __ldg(FC + jg * NCLS + c), s[c]);
        }
    }
#pragma unroll
    for (int c = 0; c < NCLS; c++) {
        s[c] += __shfl_xor_sync(0xffffffffu, s[c], 1);
        s[c] += __shfl_xor_sync(0xffffffffu, s[c], 2);
        s[c] += __shfl_xor_sync(0xffffffffu, s[c], 4);
    }
    if (g == 0) {
#pragma unroll
        for (int c = 0; c < NCLS; c++)
            out[(size_t)row * NCLS + c] = s[c] + __ldg(FCb + c);
    }
}

// ---------------- launch ----------------
extern "C" void kernel_launch(void* const* d_in, const int* in_sizes, int n_in,
                              void* d_out, int out_size) {
    const float* x    = (const float*)d_in[0];
    const float* W1   = (const float*)d_in[1];
    const float* W2   = (const float*)d_in[2];
    const float* U1   = (const float*)d_in[3];
    const float* U2   = (const float*)d_in[4];
    const float* bg   = (const float*)d_in[5];
    const float* bu   = (const float*)d_in[6];
    const float* zeta = (const float*)d_in[7];
    const float* nu   = (const float*)d_in[8];
    const float* FC   = (const float*)d_in[9];
    const float* FCb  = (const float*)d_in[10];
    float* out = (float*)d_out;

    setup_kernel<<<32, 256>>>(W1, W2, U1, U2, bg, bu, zeta, nu);
    xw_kernel<<<XW_GRID, XW_THREADS>>>(x);
    grnn_kernel<<<NGRID, NTHREADS>>>(FC, FCb, out);
}

// round 6
// speedup vs baseline: 1.6713x; 1.6713x over previous
#include <cuda_runtime.h>
#include <math.h>

// ---------------- problem constants ----------------
#define BATCH    8192
#define TSTEPS   99
#define DIN      32
#define DH       100
#define GRP      8           // lane-slices per row
#define JT       14          // hidden cols per slice (padded to 16 in xc)
#define RW       16
#define RU       25
#define RP       28          // padded rank (phase-1 accumulator width)
#define SLST     20          // U2 slice stride (words): conflict-free
#define U2ROW    160         // U2 smem row stride = 8*20
#define NCLS     6
#define NTHREADS 128
#define ROWS_CTA 32          // 128 thr / 8 grp * 2 rows
#define NGRID    (BATCH / ROWS_CTA)        // 256
#define RT_TOTAL (BATCH * TSTEPS)          // 811008
#define XW_GRID  (RT_TOTAL / 128)          // 6336
#define XW_THREADS 256

// ---------------- device-global prepped weights + scratch ----------------
__device__ float g_Wct[DIN * 128];          // [k][col], col = g*16+jl -> j=g*14+jl
__device__ float g_U1p[112 * RP];           // [slot = jl*8+g][28]
__device__ float g_U2p[RU * U2ROW];         // [r][g*20 + c]
__device__ float g_bb [112 * 2];            // interleaved (bias_gate, bias_update), j-indexed
__device__ float g_sc [2];                  // sigmoid(zeta), sigmoid(nu)
__device__ float g_xc [(size_t)RT_TOTAL * 128];   // xc[rt][128], col = g*16+jl

// ---------------- packed f32x2 FMA + tanh.approx ----------------
__device__ __forceinline__ void fma2(float2& d, float2 a, float2 b) {
    asm("fma.rn.f32x2 %0, %1, %2, %0;"
        : "+l"(reinterpret_cast<unsigned long long&>(d))
        : "l"(reinterpret_cast<unsigned long long&>(a)),
          "l"(reinterpret_cast<unsigned long long&>(b)));
}
__device__ __forceinline__ float tanha(float x) {
    float r; asm("tanh.approx.f32 %0, %1;" : "=f"(r) : "f"(x)); return r;
}
__device__ __forceinline__ float elem4(float4 v, int e) {
    return (e == 0) ? v.x : (e == 1) ? v.y : (e == 2) ? v.z : v.w;
}

// ---------------- setup: fold / pad / transpose weights ----------------
__global__ void setup_kernel(const float* __restrict__ W1, const float* __restrict__ W2,
                             const float* __restrict__ U1, const float* __restrict__ U2,
                             const float* __restrict__ bg, const float* __restrict__ bu,
                             const float* __restrict__ zeta, const float* __restrict__ nu) {
    int tid = blockIdx.x * blockDim.x + threadIdx.x;
    int nth = gridDim.x * blockDim.x;
    // Wct[k][g*16+jl] = (W1@W2)[k][g*14+jl]  (jl<14, j<100)
    for (int idx = tid; idx < DIN * 128; idx += nth) {
        int k = idx >> 7, c = idx & 127;
        int g = c >> 4, jl = c & 15;
        int j = g * JT + jl;
        float s = 0.f;
        if (jl < JT && j < DH)
            for (int r = 0; r < RW; r++) s = fmaf(W1[k * RW + r], W2[r * DH + j], s);
        g_Wct[idx] = s;
    }
    // U1p[(jl*8+g)*28 + r] = U1[g*14+jl][r]
    for (int idx = tid; idx < 112 * RP; idx += nth) {
        int slot = idx / RP, r = idx % RP;
        int jl = slot >> 3, g = slot & 7;
        int j = g * JT + jl;
        g_U1p[idx] = (j < DH && r < RU) ? U1[j * RU + r] : 0.f;
    }
    // U2p[r*160 + g*20 + c] = U2[r][g*14+c]  (c<14)
    for (int idx = tid; idx < RU * U2ROW; idx += nth) {
        int r = idx / U2ROW, w = idx % U2ROW;
        int g = w / SLST, c = w % SLST;
        int j = g * JT + c;
        g_U2p[idx] = (c < JT && j < DH) ? U2[r * DH + j] : 0.f;
    }
    for (int j = tid; j < 112; j += nth) {
        g_bb[2 * j]     = (j < DH) ? bg[j] : 0.f;
        g_bb[2 * j + 1] = (j < DH) ? bu[j] : 0.f;
    }
    if (tid == 0) {
        g_sc[0] = 1.f / (1.f + expf(-zeta[0]));
        g_sc[1] = 1.f / (1.f + expf(-nu[0]));
    }
}

// ---------------- xw GEMM: g_xc[rt][.] = x_flat[rt][0..31] @ Wct ----------------
__global__ void __launch_bounds__(XW_THREADS)
xw_kernel(const float* __restrict__ x) {
    __shared__ __align__(16) float Wcs[DIN * 128];   // 16 KB
    __shared__ __align__(16) float xts[DIN * 128];   // x transposed: [k][rt_local]

    const int tid = threadIdx.x;
    for (int i = tid; i < DIN * 128; i += XW_THREADS) Wcs[i] = g_Wct[i];

    const float4* xsrc = (const float4*)x + (size_t)blockIdx.x * 1024;
#pragma unroll
    for (int i = 0; i < 4; i++) {
        int fidx = tid * 4 + i;
        int rt_l = fidx >> 3;
        int k4   = (fidx & 7) * 4;
        float4 v = xsrc[fidx];
        xts[(k4 + 0) * 128 + rt_l] = v.x;
        xts[(k4 + 1) * 128 + rt_l] = v.y;
        xts[(k4 + 2) * 128 + rt_l] = v.z;
        xts[(k4 + 3) * 128 + rt_l] = v.w;
    }
    __syncthreads();

    const int rtg = tid >> 3;              // 0..31 (4 rt each)
    const int cg  = tid & 7;               // col chunks at cg*4 + q*32

    float2 acc[4][8];
#pragma unroll
    for (int r = 0; r < 4; r++)
#pragma unroll
        for (int i = 0; i < 8; i++) acc[r][i] = make_float2(0.f, 0.f);

#pragma unroll 4
    for (int k = 0; k < DIN; k++) {
        float4 xv = *(const float4*)(xts + k * 128 + rtg * 4);
#pragma unroll
        for (int q = 0; q < 4; q++) {
            float4 wv = *(const float4*)(Wcs + k * 128 + q * 32 + cg * 4);
            float2 wl = make_float2(wv.x, wv.y);
            float2 wh = make_float2(wv.z, wv.w);
#pragma unroll
            for (int r = 0; r < 4; r++) {
                float xk = elem4(xv, r);
                float2 x2 = make_float2(xk, xk);
                fma2(acc[r][2 * q],     x2, wl);
                fma2(acc[r][2 * q + 1], x2, wh);
            }
        }
    }
#pragma unroll
    for (int r = 0; r < 4; r++) {
        size_t rti = (size_t)blockIdx.x * 128 + rtg * 4 + r;
#pragma unroll
        for (int q = 0; q < 4; q++)
            *(float4*)(g_xc + rti * 128 + q * 32 + cg * 4) =
                make_float4(acc[r][2 * q].x, acc[r][2 * q].y,
                            acc[r][2 * q + 1].x, acc[r][2 * q + 1].y);
    }
}

// ---------------- fused recurrent kernel: RPT=2, no caps, no barriers ----------------
__global__ void __launch_bounds__(NTHREADS, 2)
grnn_kernel(const float* __restrict__ FC, const float* __restrict__ FCb,
            float* __restrict__ out) {
    __shared__ __align__(16) float U1s[112 * RP];    // 12.5 KB
    __shared__ __align__(16) float U2s[RU * U2ROW];  // 16.0 KB
    __shared__ __align__(16) float bbs[112 * 2];     // 0.9 KB

    const int tid = threadIdx.x;
    for (int i = tid; i < 112 * RP; i += NTHREADS) U1s[i] = g_U1p[i];
    for (int i = tid; i < RU * U2ROW; i += NTHREADS) U2s[i] = g_U2p[i];
    for (int i = tid; i < 112 * 2; i += NTHREADS) bbs[i] = g_bb[i];
    __syncthreads();

    const float sz = g_sc[0];
    const float sn = g_sc[1];

    const int g    = tid & 7;
    const int pr   = tid >> 3;                    // 0..15 row-pair
    const int rowA = blockIdx.x * ROWS_CTA + 2 * pr;

    const float* bbp = bbs + (g * JT) * 2;
    const float* pxA = g_xc + ((size_t)rowA * TSTEPS) * 128 + g * 16;
    const float* pxB = pxA + (size_t)TSTEPS * 128;

    float2 HA[JT / 2], HB[JT / 2];
#pragma unroll
    for (int i = 0; i < JT / 2; i++) { HA[i] = make_float2(0.f, 0.f); HB[i] = make_float2(0.f, 0.f); }

    // current xc slices, held as the c-accumulators directly
    float2 cA[8], cB[8];
    {
        float4 a0 = *(const float4*)(pxA),      a1 = *(const float4*)(pxA + 4);
        float4 a2 = *(const float4*)(pxA + 8),  a3 = *(const float4*)(pxA + 12);
        float4 b0 = *(const float4*)(pxB),      b1 = *(const float4*)(pxB + 4);
        float4 b2 = *(const float4*)(pxB + 8),  b3 = *(const float4*)(pxB + 12);
        cA[0] = make_float2(a0.x, a0.y); cA[1] = make_float2(a0.z, a0.w);
        cA[2] = make_float2(a1.x, a1.y); cA[3] = make_float2(a1.z, a1.w);
        cA[4] = make_float2(a2.x, a2.y); cA[5] = make_float2(a2.z, a2.w);
        cA[6] = make_float2(a3.x, a3.y); cA[7] = make_float2(a3.z, a3.w);
        cB[0] = make_float2(b0.x, b0.y); cB[1] = make_float2(b0.z, b0.w);
        cB[2] = make_float2(b1.x, b1.y); cB[3] = make_float2(b1.z, b1.w);
        cB[4] = make_float2(b2.x, b2.y); cB[5] = make_float2(b2.z, b2.w);
        cB[6] = make_float2(b3.x, b3.y); cB[7] = make_float2(b3.z, b3.w);
    }

    for (int t = 0; t < TSTEPS; t++) {
        // prefetch next step's xc (repeat of current on last step)
        const int off = (t + 1 < TSTEPS) ? (t + 1) * 128 : t * 128;
        float4 na0 = *(const float4*)(pxA + off),      na1 = *(const float4*)(pxA + off + 4);
        float4 na2 = *(const float4*)(pxA + off + 8),  na3 = *(const float4*)(pxA + off + 12);
        float4 nb0 = *(const float4*)(pxB + off),      nb1 = *(const float4*)(pxB + off + 4);
        float4 nb2 = *(const float4*)(pxB + off + 8),  nb3 = *(const float4*)(pxB + off + 12);

        // ---- phase 1: partial Hp = H @ U1 (weights shared across both rows) ----
        float2 pa[RP / 2], pb[RP / 2];
#pragma unroll
        for (int i = 0; i < RP / 2; i++) { pa[i] = make_float2(0.f, 0.f); pb[i] = make_float2(0.f, 0.f); }
#pragma unroll
        for (int jl = 0; jl < JT; jl++) {
            float hA = (jl & 1) ? HA[jl >> 1].y : HA[jl >> 1].x;
            float hB = (jl & 1) ? HB[jl >> 1].y : HB[jl >> 1].x;
            float2 hAv = make_float2(hA, hA);
            float2 hBv = make_float2(hB, hB);
            const float4* urow = (const float4*)(U1s + (jl * GRP + g) * RP);
#pragma unroll
            for (int q = 0; q < 7; q++) {
                float4 u = urow[q];
                float2 ul = make_float2(u.x, u.y);
                float2 uh = make_float2(u.z, u.w);
                fma2(pa[2 * q],     hAv, ul);
                fma2(pa[2 * q + 1], hAv, uh);
                fma2(pb[2 * q],     hBv, ul);
                fma2(pb[2 * q + 1], hBv, uh);
            }
        }
        // ---- butterfly all-reduce over the 8 slice-lanes (only r<26 matter) ----
#pragma unroll
        for (int i = 0; i < 13; i++) {
            float ax = pa[i].x, ay = pa[i].y, bx = pb[i].x, by = pb[i].y;
            ax += __shfl_xor_sync(0xffffffffu, ax, 1);
            ay += __shfl_xor_sync(0xffffffffu, ay, 1);
            bx += __shfl_xor_sync(0xffffffffu, bx, 1);
            by += __shfl_xor_sync(0xffffffffu, by, 1);
            ax += __shfl_xor_sync(0xffffffffu, ax, 2);
            ay += __shfl_xor_sync(0xffffffffu, ay, 2);
            bx += __shfl_xor_sync(0xffffffffu, bx, 2);
            by += __shfl_xor_sync(0xffffffffu, by, 2);
            ax += __shfl_xor_sync(0xffffffffu, ax, 4);
            ay += __shfl_xor_sync(0xffffffffu, ay, 4);
            bx += __shfl_xor_sync(0xffffffffu, bx, 4);
            by += __shfl_xor_sync(0xffffffffu, by, 4);
            pa[i] = make_float2(ax, ay);
            pb[i] = make_float2(bx, by);
        }

        // ---- phase 2: c += Hp @ U2 (slice), both rows ----
#pragma unroll
        for (int r = 0; r < RU; r++) {
            float hpA = (r & 1) ? pa[r >> 1].y : pa[r >> 1].x;
            float hpB = (r & 1) ? pb[r >> 1].y : pb[r >> 1].x;
            float2 hAv = make_float2(hpA, hpA);
            float2 hBv = make_float2(hpB, hpB);
            const float4* u = (const float4*)(U2s + r * U2ROW + g * SLST);
#pragma unroll
            for (int q = 0; q < 4; q++) {
                float4 uv = u[q];
                float2 ul = make_float2(uv.x, uv.y);
                float2 uh = make_float2(uv.z, uv.w);
                fma2(cA[2 * q],     hAv, ul);
                fma2(cA[2 * q + 1], hAv, uh);
                fma2(cB[2 * q],     hBv, ul);
                fma2(cB[2 * q + 1], hBv, uh);
            }
        }

        // ---- elementwise gate/update (sigmoid = 0.5*tanh(z/2)+0.5) ----
#pragma unroll
        for (int jl = 0; jl < JT; jl++) {
            float2 bb = *(const float2*)(bbp + 2 * jl);
            {
                float cc = (jl & 1) ? cA[jl >> 1].y : cA[jl >> 1].x;
                float gg = fmaf(0.5f, tanha(0.5f * (cc + bb.x)), 0.5f);
                float hh = tanha(cc + bb.y);
                float ho = (jl & 1) ? HA[jl >> 1].y : HA[jl >> 1].x;
                float hn = fmaf(gg, ho - sz, fmaf(sn, hh, sz));
                if (jl & 1) HA[jl >> 1].y = hn; else HA[jl >> 1].x = hn;
            }
            {
                float cc = (jl & 1) ? cB[jl >> 1].y : cB[jl >> 1].x;
                float gg = fmaf(0.5f, tanha(0.5f * (cc + bb.x)), 0.5f);
                float hh = tanha(cc + bb.y);
                float ho = (jl & 1) ? HB[jl >> 1].y : HB[jl >> 1].x;
                float hn = fmaf(gg, ho - sz, fmaf(sn, hh, sz));
                if (jl & 1) HB[jl >> 1].y = hn; else HB[jl >> 1].x = hn;
            }
        }

        // ---- roll in prefetched xc as next step's c-init ----
        cA[0] = make_float2(na0.x, na0.y); cA[1] = make_float2(na0.z, na0.w);
        cA[2] = make_float2(na1.x, na1.y); cA[3] = make_float2(na1.z, na1.w);
        cA[4] = make_float2(na2.x, na2.y); cA[5] = make_float2(na2.z, na2.w);
        cA[6] = make_float2(na3.x, na3.y); cA[7] = make_float2(na3.z, na3.w);
        cB[0] = make_float2(nb0.x, nb0.y); cB[1] = make_float2(nb0.z, nb0.w);
        cB[2] = make_float2(nb1.x, nb1.y); cB[3] = make_float2(nb1.z, nb1.w);
        cB[4] = make_float2(nb2.x, nb2.y); cB[5] = make_float2(nb2.z, nb2.w);
        cB[6] = make_float2(nb3.x, nb3.y); cB[7] = make_float2(nb3.z, nb3.w);
    }

    // ---- epilogue: score = H @ FC + FCbias ----
    float sA[NCLS], sB[NCLS];
#pragma unroll
    for (int c = 0; c < NCLS; c++) { sA[c] = 0.f; sB[c] = 0.f; }
#pragma unroll
    for (int jl = 0; jl < JT; jl++) {
        int jg = g * JT + jl;
        if (jg < DH) {
            float hA = (jl & 1) ? HA[jl >> 1].y : HA[jl >> 1].x;
            float hB = (jl & 1) ? HB[jl >> 1].y : HB[jl >> 1].x;
#pragma unroll
            for (int c = 0; c < NCLS; c++) {
                float fc = __ldg(FC + jg * NCLS + c);
                sA[c] = fmaf(hA, fc, sA[c]);
                sB[c] = fmaf(hB, fc, sB[c]);
            }
        }
    }
#pragma unroll
    for (int c = 0; c < NCLS; c++) {
        sA[c] += __shfl_xor_sync(0xffffffffu, sA[c], 1);
        sB[c] += __shfl_xor_sync(0xffffffffu, sB[c], 1);
        sA[c] += __shfl_xor_sync(0xffffffffu, sA[c], 2);
        sB[c] += __shfl_xor_sync(0xffffffffu, sB[c], 2);
        sA[c] += __shfl_xor_sync(0xffffffffu, sA[c], 4);
        sB[c] += __shfl_xor_sync(0xffffffffu, sB[c], 4);
    }
    if (g == 0) {
#pragma unroll
        for (int c = 0; c < NCLS; c++) {
            float fb = __ldg(FCb + c);
            out[(size_t)rowA * NCLS + c]       = sA[c] + fb;
            out[(size_t)(rowA + 1) * NCLS + c] = sB[c] + fb;
        }
    }
}

// ---------------- launch ----------------
extern "C" void kernel_launch(void* const* d_in, const int* in_sizes, int n_in,
                              void* d_out, int out_size) {
    const float* x    = (const float*)d_in[0];
    const float* W1   = (const float*)d_in[1];
    const float* W2   = (const float*)d_in[2];
    const float* U1   = (const float*)d_in[3];
    const float* U2   = (const float*)d_in[4];
    const float* bg   = (const float*)d_in[5];
    const float* bu   = (const float*)d_in[6];
    const float* zeta = (const float*)d_in[7];
    const float* nu   = (const float*)d_in[8];
    const float* FC   = (const float*)d_in[9];
    const float* FCb  = (const float*)d_in[10];
    float* out = (float*)d_out;

    setup_kernel<<<32, 256>>>(W1, W2, U1, U2, bg, bu, zeta, nu);
    xw_kernel<<<XW_GRID, XW_THREADS>>>(x);
    grnn_kernel<<<NGRID, NTHREADS>>>(FC, FCb, out);
}